// round 16
// baseline (speedup 1.0000x reference)
#include <cuda_runtime.h>
#include <cuda_bf16.h>
#include <cstdint>

#define EMAX 65536
#define GMAX 64
#define MT   128      // edges per upd CTA
#define MT2  64       // edges per msg CTA
#define MSTR (MT + 4) // 132
#define IT   64       // edges per init CTA
#define ISTR (IT + 4) // 68

__device__ float g_x[(size_t)EMAX * 64];
__device__ float g_aggr[(size_t)EMAX * 64];
__device__ float g_deg[EMAX];
__device__ int   g_bt[EMAX];
__device__ float g_gsum[GMAX * 64];
__device__ float g_gcnt[GMAX];

// fragment-ordered pre-converted weights (k_msg fragment images)
__device__ uint4 g_w1f[2][2][4][12][32];
__device__ uint4 g_w2f[2][2][4][4][32];

typedef unsigned long long u64;
typedef unsigned int       u32;

__device__ __forceinline__ u64 pack2(float x) {
    u64 r; asm("mov.b64 %0, {%1, %2};" : "=l"(r) : "f"(x), "f"(x)); return r;
}
__device__ __forceinline__ void unpack2(u64 v, float& lo, float& hi) {
    asm("mov.b64 {%0, %1}, %2;" : "=f"(lo), "=f"(hi) : "l"(v));
}
__device__ __forceinline__ float gethalf(u64 v, int which) {
    float lo, hi; unpack2(v, lo, hi); return which ? hi : lo;
}
__device__ __forceinline__ u64 ffma2(u64 a, u64 b, u64 c) {
    u64 d; asm("fma.rn.f32x2 %0, %1, %2, %3;" : "=l"(d) : "l"(a), "l"(b), "l"(c)); return d;
}
__device__ __forceinline__ float silu_f(float v) {
    return __fdividef(v, 1.f + __expf(-v));
}

__device__ __forceinline__ void cpys(float* dst, const float* __restrict__ src, int n) {
    const float4* s4 = (const float4*)src; float4* d4 = (float4*)dst;
    for (int i = threadIdx.x; i < (n >> 2); i += blockDim.x) d4[i] = s4[i];
}

__device__ __forceinline__ u32 smem_u32(const void* p) {
    u32 a;
    asm("{ .reg .u64 t; cvta.to.shared.u64 t, %1; cvt.u32.u64 %0, t; }" : "=r"(a) : "l"(p));
    return a;
}

// mma.sync m16n8k16 bf16 (generic HMMA)
__device__ __forceinline__ void mma_bf16(float d[4], u32 a0, u32 a1, u32 a2, u32 a3,
                                         u32 b0, u32 b1) {
    asm volatile("mma.sync.aligned.m16n8k16.row.col.f32.bf16.bf16.f32 "
                 "{%0,%1,%2,%3}, {%4,%5,%6,%7}, {%8,%9}, {%0,%1,%2,%3};"
                 : "+f"(d[0]), "+f"(d[1]), "+f"(d[2]), "+f"(d[3])
                 : "r"(a0), "r"(a1), "r"(a2), "r"(a3), "r"(b0), "r"(b1));
}

#define LDMX4(r, addr) \
    asm volatile("ldmatrix.sync.aligned.m8n8.x4.shared.b16 {%0,%1,%2,%3}, [%4];" \
                 : "=r"((r)[0]), "=r"((r)[1]), "=r"((r)[2]), "=r"((r)[3]) : "r"(addr))

// ---------------- k_msg SMEM layout (bytes), 64 edges/CTA; H overlays dead A ----------------
#define SA 200   // 400 B = 16 mod 128 -> ldmatrix conflict-free
#define SH 72    // 144 B = 16 mod 128
#define SM_AH   0
#define SM_AL   25600
#define SM_HH   0
#define SM_HL   9216
#define SM_B1V  51200
#define SM_B2V  51456
#define SM_DSV  51712
#define SM_MSG_TOTAL 52224

__device__ __forceinline__ void split_store(char* smb, int hio, int loo, int stride,
                                            int r, int k, float f0, float f1) {
    __nv_bfloat162 h = __floats2bfloat162_rn(f0, f1);
    __nv_bfloat162 l = __floats2bfloat162_rn(f0 - __bfloat162float(h.x),
                                             f1 - __bfloat162float(h.y));
    int off = (r * stride + k) * 2;
    *(u32*)(smb + hio + off) = *(u32*)&h;
    *(u32*)(smb + loo + off) = *(u32*)&l;
}

__device__ __forceinline__ void conv_row16(char* smb, const float* __restrict__ src,
                                           int r, int kbase) {
    const float4* s4 = (const float4*)src;
    #pragma unroll
    for (int j = 0; j < 16; j++) {
        float4 v = s4[j];
        int k = kbase + 4 * j;
        split_store(smb, SM_AH, SM_AL, SA, r, k, v.x, v.y);
        split_store(smb, SM_AH, SM_AL, SA, r, k + 2, v.z, v.w);
    }
}

// ---------------- kernels ----------------

__global__ void k_zero(int E) {
    int stride = gridDim.x * blockDim.x;
    for (int i = blockIdx.x * blockDim.x + threadIdx.x; i < E * 64; i += stride)
        g_aggr[i] = 0.f;
    int i = blockIdx.x * blockDim.x + threadIdx.x;
    if (i < E) g_deg[i] = 0.f;
    if (i < GMAX * 64) g_gsum[i] = 0.f;
    if (i < GMAX) g_gcnt[i] = 0.f;
}

__global__ void k_deg(const int* __restrict__ bei, int BE) {
    int b = blockIdx.x * blockDim.x + threadIdx.x;
    if (b < BE) atomicAdd(&g_deg[bei[BE + b]], 1.f);
}

// Pre-pack W1/W2 (hi/lo splits) into mma-b-fragment order. 8192 threads.
__global__ void k_wconv(const float* __restrict__ mw1, const float* __restrict__ mw2) {
    int i = blockIdx.x * blockDim.x + threadIdx.x;
    int lane = i & 31;
    int g = lane >> 2, qi = lane & 3;

    auto packfrag = [&](const float* W, int s, int ks, int img) {
        uint4 v; u32* pv = (u32*)&v;
        #pragma unroll
        for (int nt = 0; nt < 2; nt++) {
            int n = s * 16 + nt * 8 + g;
            #pragma unroll
            for (int bi = 0; bi < 2; bi++) {
                int k = ks * 16 + bi * 8 + 2 * qi;
                float w0 = W[k * 64 + n], w1v = W[(k + 1) * 64 + n];
                __nv_bfloat16 h0 = __float2bfloat16_rn(w0), h1 = __float2bfloat16_rn(w1v);
                __nv_bfloat162 o;
                if (img == 0) { o.x = h0; o.y = h1; }
                else {
                    o.x = __float2bfloat16_rn(w0 - __bfloat162float(h0));
                    o.y = __float2bfloat16_rn(w1v - __bfloat162float(h1));
                }
                pv[nt * 2 + bi] = *(u32*)&o;
            }
        }
        return v;
    };

    if (i < 6144) {
        int t = i >> 5;
        int ks = t % 12; t /= 12;
        int s = t & 3; t >>= 2;
        int img = t & 1, l = t >> 1;
        g_w1f[l][img][s][ks][lane] = packfrag(mw1 + l * 12288, s, ks, img);
        return;
    }
    int i2 = i - 6144;
    if (i2 >= 0 && i2 < 2048) {
        int t = i2 >> 5;
        int ks = t & 3; t >>= 2;
        int s = t & 3; t >>= 2;
        int img = t & 1, l = t >> 1;
        g_w2f[l][img][s][ks][lane] = packfrag(mw2 + l * 4096, s, ks, img);
    }
}

// ---------- scalar GEMM pieces (init/upd) ----------

template<int KK, int STR>
__device__ __forceinline__ void gemm_acc(const float* As, const float* Ws,
                                         int eg, int cg, u64 acc[2][4]) {
    const float* ap = As + eg * 4;
    const float* wp = Ws + cg * 4;
    #pragma unroll 4
    for (int k = 0; k < KK; k++) {
        ulonglong2 av = *(const ulonglong2*)(ap + k * STR);
        float4 wv = *(const float4*)(wp + k * 64);
        u64 w0 = pack2(wv.x), w1 = pack2(wv.y), w2 = pack2(wv.z), w3 = pack2(wv.w);
        acc[0][0] = ffma2(av.x, w0, acc[0][0]); acc[0][1] = ffma2(av.x, w1, acc[0][1]);
        acc[0][2] = ffma2(av.x, w2, acc[0][2]); acc[0][3] = ffma2(av.x, w3, acc[0][3]);
        acc[1][0] = ffma2(av.y, w0, acc[1][0]); acc[1][1] = ffma2(av.y, w1, acc[1][1]);
        acc[1][2] = ffma2(av.y, w2, acc[1][2]); acc[1][3] = ffma2(av.y, w3, acc[1][3]);
    }
}

__device__ __forceinline__ void bias_init(const float* __restrict__ b, int cg, u64 acc[2][4]) {
    float4 bv = *(const float4*)(b + cg * 4);
    acc[0][0] = acc[1][0] = pack2(bv.x);
    acc[0][1] = acc[1][1] = pack2(bv.y);
    acc[0][2] = acc[1][2] = pack2(bv.z);
    acc[0][3] = acc[1][3] = pack2(bv.w);
}

template<int STR>
__device__ __forceinline__ void silu_store(const u64 acc[2][4], float* Hs, int eg, int cg) {
    #pragma unroll
    for (int c = 0; c < 4; c++) {
        float x0, x1, x2, x3;
        unpack2(acc[0][c], x0, x1); unpack2(acc[1][c], x2, x3);
        float4 hv = make_float4(silu_f(x0), silu_f(x1), silu_f(x2), silu_f(x3));
        *(float4*)(Hs + (cg * 4 + c) * STR + eg * 4) = hv;
    }
}

// bond_init: 64 edges/CTA, 256 threads (scalar)
extern "C" __global__ void __launch_bounds__(256, 1)
k_init(const float* __restrict__ af, const int* __restrict__ eidx,
       const float* __restrict__ iw1, const float* __restrict__ ib1,
       const float* __restrict__ iw2, const float* __restrict__ ib2, int E) {
    extern __shared__ float sm[];
    float* W1s = sm;
    float* W2s = sm + 16384;
    float* As  = sm + 20480;
    float* Hs  = sm + 20480 + 17408;
    cpys(W1s, iw1, 16384); cpys(W2s, iw2, 4096);

    int tid = threadIdx.x;
    int e_loc = tid >> 2, p = tid & 3;
    int e = blockIdx.x * IT + e_loc;
    int ec = (e < E) ? e : 0;
    int r = eidx[ec], c = eidx[E + ec];
    const float* hi = af + (size_t)r * 128;
    const float* hj = af + (size_t)c * 128;
    #pragma unroll
    for (int i = 0; i < 8; i++) {
        int j = p + 4 * i;
        float4 v = ((const float4*)hi)[j];
        int k = 4 * j;
        As[(k + 0) * ISTR + e_loc] = v.x; As[(k + 1) * ISTR + e_loc] = v.y;
        As[(k + 2) * ISTR + e_loc] = v.z; As[(k + 3) * ISTR + e_loc] = v.w;
    }
    #pragma unroll
    for (int i = 0; i < 8; i++) {
        int j = p + 4 * i;
        float4 v = ((const float4*)hj)[j];
        int k = 128 + 4 * j;
        As[(k + 0) * ISTR + e_loc] = v.x; As[(k + 1) * ISTR + e_loc] = v.y;
        As[(k + 2) * ISTR + e_loc] = v.z; As[(k + 3) * ISTR + e_loc] = v.w;
    }
    __syncthreads();

    {
        float dot = 0.f, ni = 0.f, nj = 0.f;
        #pragma unroll 8
        for (int t = 0; t < 32; t++) {
            int k = p * 32 + t;
            float a = As[k * ISTR + e_loc];
            float b = As[(128 + k) * ISTR + e_loc];
            dot += a * b; ni += a * a; nj += b * b;
        }
        dot += __shfl_xor_sync(~0u, dot, 1); dot += __shfl_xor_sync(~0u, dot, 2);
        ni  += __shfl_xor_sync(~0u, ni, 1);  ni  += __shfl_xor_sync(~0u, ni, 2);
        nj  += __shfl_xor_sync(~0u, nj, 1);  nj  += __shfl_xor_sync(~0u, nj, 2);
        if (p == 0 && e < E) {
            float a = fmaxf(sqrtf(ni), 1e-8f), b = fmaxf(sqrtf(nj), 1e-8f);
            float sim = dot / (a * b);
            int bt = 0;
            if (sim > 0.8f) bt = 1;
            if (sim > 0.9f) bt = 2;
            if (sim < 0.3f) bt = 3;
            g_bt[e] = bt;
        }
    }

    int eg = tid >> 4, cg = tid & 15;
    u64 a1[2][4]; bias_init(ib1, cg, a1);
    gemm_acc<256, ISTR>(As, W1s, eg, cg, a1);
    silu_store<ISTR>(a1, Hs, eg, cg);
    __syncthreads();
    u64 o[2][4]; bias_init(ib2, cg, o);
    gemm_acc<64, ISTR>(Hs, W2s, eg, cg, o);

    int ebase = blockIdx.x * IT + eg * 4;
    #pragma unroll
    for (int j = 0; j < 4; j++) {
        if (ebase + j < E) {
            float4 v;
            v.x = gethalf(o[j >> 1][0], j & 1); v.y = gethalf(o[j >> 1][1], j & 1);
            v.z = gethalf(o[j >> 1][2], j & 1); v.w = gethalf(o[j >> 1][3], j & 1);
            *(float4*)(g_x + (size_t)(ebase + j) * 64 + cg * 4) = v;
        }
    }
}

// ---------- HMMA message MLP: 64 edges/CTA, 256 threads, 3 CTAs/SM ----------
extern "C" __global__ void __launch_bounds__(256, 3)
k_msg(const int* __restrict__ bei, const float* __restrict__ embl, int layer,
      const float* __restrict__ mb1, const float* __restrict__ mb2, int BE) {
    extern __shared__ char smb[];
    u32 sb = smem_u32(smb);
    int tid = threadIdx.x, wid = tid >> 5, lane = tid & 31;
    int g = lane >> 2, qi = lane & 3;
    int* ds = (int*)(smb + SM_DSV);
    float* b1s = (float*)(smb + SM_B1V);
    float* b2s = (float*)(smb + SM_B2V);

    // gather: 3 sources x 64 rows over threads 0..191; 192..255 load biases
    int ebase0 = blockIdx.x * MT2;
    if (tid < 192) {
        int src = tid >> 6, row = tid & 63;
        int e = ebase0 + row;
        int ec = (e < BE) ? e : 0;
        if (src == 0) {
            int d = bei[BE + ec];
            ds[row] = d;
            conv_row16(smb, g_x + (size_t)d * 64, row, 0);
        } else if (src == 1) {
            int s = bei[ec];
            conv_row16(smb, g_x + (size_t)s * 64, row, 64);
        } else {
            int d = bei[BE + ec];
            conv_row16(smb, embl + g_bt[d] * 64, row, 128);
        }
    } else {
        int j = tid - 192;
        b1s[j] = mb1[j];
        b2s[j] = mb2[j];
    }
    __syncthreads();

    int mbase = (wid & 3) * 16;
    int ns0 = (wid >> 2) * 2;
    int nbase = ns0 * 16;
    int a_row = lane & 15;
    int a_koff = (lane >> 4) * 8;

    float d_[4][4];
    #pragma unroll
    for (int nt = 0; nt < 4; nt++)
        #pragma unroll
        for (int x = 0; x < 4; x++) d_[nt][x] = 0.f;

    // GEMM1: 3 splits x 12 ksteps, K=192
    {
        const int AIMG[3] = {SM_AH, SM_AH, SM_AL};
        const int BIMG[3] = {0, 1, 0};
        #pragma unroll 1
        for (int sp = 0; sp < 3; sp++) {
            u32 Ab = sb + AIMG[sp];
            const uint4* B0 = &g_w1f[layer][BIMG[sp]][ns0][0][lane];
            const uint4* B1 = &g_w1f[layer][BIMG[sp]][ns0 + 1][0][lane];
            #pragma unroll 2
            for (int ks = 0; ks < 12; ks++) {
                int k0 = ks * 16;
                uint4 bv0 = __ldg(B0 + ks * 32);
                uint4 bv1 = __ldg(B1 + ks * 32);
                u32 af[4];
                LDMX4(af, Ab + ((mbase + a_row) * SA + k0 + a_koff) * 2);
                mma_bf16(d_[0], af[0], af[1], af[2], af[3], bv0.x, bv0.y);
                mma_bf16(d_[1], af[0], af[1], af[2], af[3], bv0.z, bv0.w);
                mma_bf16(d_[2], af[0], af[1], af[2], af[3], bv1.x, bv1.y);
                mma_bf16(d_[3], af[0], af[1], af[2], af[3], bv1.z, bv1.w);
            }
        }
    }
    __syncthreads();   // A dead; H overlays it

    // epilogue1: bias + silu + split into H
    #pragma unroll
    for (int nt = 0; nt < 4; nt++) {
        int r0 = mbase + g;
        int c0 = nbase + nt * 8 + 2 * qi;
        float bA = b1s[c0], bB = b1s[c0 + 1];
        float f0 = silu_f(d_[nt][0] + bA), f1 = silu_f(d_[nt][1] + bB);
        float f2 = silu_f(d_[nt][2] + bA), f3 = silu_f(d_[nt][3] + bB);
        split_store(smb, SM_HH, SM_HL, SH, r0, c0, f0, f1);
        split_store(smb, SM_HH, SM_HL, SH, r0 + 8, c0, f2, f3);
    }
    __syncthreads();

    // GEMM2: K=64, 3 splits x 4 ksteps
    #pragma unroll
    for (int nt = 0; nt < 4; nt++)
        #pragma unroll
        for (int x = 0; x < 4; x++) d_[nt][x] = 0.f;
    {
        const int AIMG2[3] = {SM_HH, SM_HH, SM_HL};
        const int BIMG2[3] = {0, 1, 0};
        #pragma unroll 1
        for (int sp = 0; sp < 3; sp++) {
            u32 Ab = sb + AIMG2[sp];
            const uint4* B0 = &g_w2f[layer][BIMG2[sp]][ns0][0][lane];
            const uint4* B1 = &g_w2f[layer][BIMG2[sp]][ns0 + 1][0][lane];
            #pragma unroll 2
            for (int ks = 0; ks < 4; ks++) {
                int k0 = ks * 16;
                uint4 bv0 = __ldg(B0 + ks * 32);
                uint4 bv1 = __ldg(B1 + ks * 32);
                u32 af[4];
                LDMX4(af, Ab + ((mbase + a_row) * SH + k0 + a_koff) * 2);
                mma_bf16(d_[0], af[0], af[1], af[2], af[3], bv0.x, bv0.y);
                mma_bf16(d_[1], af[0], af[1], af[2], af[3], bv0.z, bv0.w);
                mma_bf16(d_[2], af[0], af[1], af[2], af[3], bv1.x, bv1.y);
                mma_bf16(d_[3], af[0], af[1], af[2], af[3], bv1.z, bv1.w);
            }
        }
    }

    // epilogue2: bias + RED v2 scatter-add to aggr[dst]
    {
        int r0 = mbase + g;
        int dd0 = ds[r0], dd1 = ds[r0 + 8];
        bool v0 = (ebase0 + r0 < BE), v1 = (ebase0 + r0 + 8 < BE);
        #pragma unroll
        for (int nt = 0; nt < 4; nt++) {
            int c0 = nbase + nt * 8 + 2 * qi;
            float bA = b2s[c0], bB = b2s[c0 + 1];
            if (v0) {
                asm volatile("red.global.add.v2.f32 [%0], {%1,%2};"
                             :: "l"(g_aggr + (size_t)dd0 * 64 + c0),
                                "f"(d_[nt][0] + bA), "f"(d_[nt][1] + bB) : "memory");
            }
            if (v1) {
                asm volatile("red.global.add.v2.f32 [%0], {%1,%2};"
                             :: "l"(g_aggr + (size_t)dd1 * 64 + c0),
                                "f"(d_[nt][2] + bA), "f"(d_[nt][3] + bB) : "memory");
            }
        }
    }
}

// update MLP: 128 edges/CTA, 512 threads (scalar); zeroes aggr after reading.
extern "C" __global__ void __launch_bounds__(512, 1)
k_upd(const float* __restrict__ uw1, const float* __restrict__ ub1,
      const float* __restrict__ uw2, const float* __restrict__ ub2, int E) {
    extern __shared__ float sm[];
    float* W1s = sm;
    float* W2s = sm + 8192;
    float* As  = sm + 12288;
    float* Hs  = sm + 12288 + 16896;
    cpys(W1s, uw1, 8192); cpys(W2s, uw2, 4096);

    int tid = threadIdx.x;
    int e_loc = tid >> 2, p = tid & 3;
    int e = blockIdx.x * MT + e_loc;
    int ec = (e < E) ? e : 0;
    float rdiv = 1.f / fmaxf(g_deg[ec], 1.f);
    float* arow = g_aggr + (size_t)ec * 64;
    const float* xrow = g_x + (size_t)ec * 64;
    #pragma unroll
    for (int i = 0; i < 4; i++) {
        int j = p + 4 * i;
        float4 v = ((const float4*)arow)[j];
        int k = 4 * j;
        As[(k + 0) * MSTR + e_loc] = v.x * rdiv; As[(k + 1) * MSTR + e_loc] = v.y * rdiv;
        As[(k + 2) * MSTR + e_loc] = v.z * rdiv; As[(k + 3) * MSTR + e_loc] = v.w * rdiv;
        if (e < E) ((float4*)arow)[j] = make_float4(0.f, 0.f, 0.f, 0.f);
    }
    #pragma unroll
    for (int i = 0; i < 4; i++) {
        int j = p + 4 * i;
        float4 v = ((const float4*)xrow)[j];
        int k = 64 + 4 * j;
        As[(k + 0) * MSTR + e_loc] = v.x; As[(k + 1) * MSTR + e_loc] = v.y;
        As[(k + 2) * MSTR + e_loc] = v.z; As[(k + 3) * MSTR + e_loc] = v.w;
    }
    __syncthreads();

    int eg = tid >> 4, cg = tid & 15;
    u64 a1[2][4]; bias_init(ub1, cg, a1);
    gemm_acc<128, MSTR>(As, W1s, eg, cg, a1);
    silu_store<MSTR>(a1, Hs, eg, cg);
    __syncthreads();
    u64 o[2][4]; bias_init(ub2, cg, o);
    gemm_acc<64, MSTR>(Hs, W2s, eg, cg, o);

    int ebase = blockIdx.x * MT + eg * 4;
    #pragma unroll
    for (int j = 0; j < 4; j++) {
        if (ebase + j < E) {
            float* xp = g_x + (size_t)(ebase + j) * 64 + cg * 4;
            float4 xv = *(float4*)xp;
            xv.x += gethalf(o[j >> 1][0], j & 1); xv.y += gethalf(o[j >> 1][1], j & 1);
            xv.z += gethalf(o[j >> 1][2], j & 1); xv.w += gethalf(o[j >> 1][3], j & 1);
            *(float4*)xp = xv;
        }
    }
}

// pooling: per-edge float4 RED of x into gsum; cc==0 thread also counts the edge.
__global__ void k_pool2(const int* __restrict__ eidx, const int* __restrict__ batch, int E) {
    int i = blockIdx.x * blockDim.x + threadIdx.x;
    if (i >= E * 16) return;
    int e = i >> 4, cc = i & 15;
    int gph = batch[eidx[e]];
    if (cc == 0) atomicAdd(&g_gcnt[gph], 1.f);
    float4 v = ((const float4*)g_x)[(size_t)e * 16 + cc];
    float* dst = g_gsum + gph * 64 + cc * 4;
    asm volatile("red.global.add.v4.f32 [%0], {%1,%2,%3,%4};"
                 :: "l"(dst), "f"(v.x), "f"(v.y), "f"(v.z), "f"(v.w) : "memory");
}

// fused final: copy x to out[0..E*64) and write pooled features at out[E*64..]
__global__ void k_fin2(float* __restrict__ out, int E, int G) {
    int i = blockIdx.x * blockDim.x + threadIdx.x;
    int n4 = E * 16;
    const float4* src = (const float4*)g_x;
    float4* dst = (float4*)out;
    for (int j = i; j < n4; j += gridDim.x * blockDim.x) dst[j] = src[j];
    if (i < G * 64) out[(size_t)E * 64 + i] = g_gsum[i] / fmaxf(g_gcnt[i >> 6], 1.f);
}

// ---------------- host launcher ----------------

extern "C" void kernel_launch(void* const* d_in, const int* in_sizes, int n_in,
                              void* d_out, int out_size) {
    const float* af    = (const float*)d_in[0];
    const int*   batch = (const int*)d_in[3];
    const int*   eidx  = (const int*)d_in[4];
    const int*   bei   = (const int*)d_in[5];
    const float* iw1 = (const float*)d_in[6];
    const float* ib1 = (const float*)d_in[7];
    const float* iw2 = (const float*)d_in[8];
    const float* ib2 = (const float*)d_in[9];
    const float* emb = (const float*)d_in[10];
    const float* mw1 = (const float*)d_in[11];
    const float* mb1 = (const float*)d_in[12];
    const float* mw2 = (const float*)d_in[13];
    const float* mb2 = (const float*)d_in[14];
    const float* uw1 = (const float*)d_in[15];
    const float* ub1 = (const float*)d_in[16];
    const float* uw2 = (const float*)d_in[17];
    const float* ub2 = (const float*)d_in[18];

    int E  = in_sizes[4] / 2;
    int BE = in_sizes[5] / 2;
    int G  = out_size / 64 - E;

    const int SH_INIT = (16384 + 4096 + 256 * ISTR + 64 * ISTR) * 4;
    const int SH_UPD  = (8192 + 4096 + 128 * MSTR + 64 * MSTR) * 4;
    cudaFuncSetAttribute(k_init, cudaFuncAttributeMaxDynamicSharedMemorySize, SH_INIT);
    cudaFuncSetAttribute(k_msg,  cudaFuncAttributeMaxDynamicSharedMemorySize, SM_MSG_TOTAL);
    cudaFuncSetAttribute(k_upd,  cudaFuncAttributeMaxDynamicSharedMemorySize, SH_UPD);

    int gI = (E + IT - 1) / IT;
    int gM = (BE + MT2 - 1) / MT2;
    int gU = (E + MT - 1) / MT;
    int gBE256 = (BE + 255) / 256;

    k_zero<<<2048, 256>>>(E);
    k_wconv<<<32, 256>>>(mw1, mw2);
    k_init<<<gI, 256, SH_INIT>>>(af, eidx, iw1, ib1, iw2, ib2, E);
    k_deg<<<gBE256, 256>>>(bei, BE);

    for (int l = 0; l < 2; l++) {
        k_msg<<<gM, 256, SM_MSG_TOTAL>>>(bei, emb + l * 320, l,
                                         mb1 + l * 64, mb2 + l * 64, BE);
        k_upd<<<gU, 512, SH_UPD>>>(uw1 + l * 8192, ub1 + l * 64,
                                   uw2 + l * 4096, ub2 + l * 64, E);
    }

    k_pool2<<<(E * 16 + 255) / 256, 256>>>(eidx, batch, E);
    k_fin2<<<1024, 256>>>((float*)d_out, E, G);
}

// round 17
// speedup vs baseline: 1.2279x; 1.2279x over previous
#include <cuda_runtime.h>
#include <cuda_bf16.h>
#include <cstdint>

#define EMAX 65536
#define GMAX 64
#define MT   128      // edges per msg/upd CTA
#define MSTR (MT + 4) // 132
#define IT   64       // edges per init CTA
#define ISTR (IT + 4) // 68

__device__ float g_x[(size_t)EMAX * 64];
__device__ float g_aggr[(size_t)EMAX * 64];
__device__ float g_deg[EMAX];
__device__ int   g_bt[EMAX];
__device__ float g_gsum[GMAX * 64];
__device__ float g_gcnt[GMAX];

// fragment-ordered pre-converted weights (k_msg fragment images)
__device__ uint4 g_w1f[2][2][4][12][32];
__device__ uint4 g_w2f[2][2][4][4][32];
// precomputed te @ W1[128:192] per layer/bond-type (fp32, exact)
__device__ float g_te[2][4][64];

typedef unsigned long long u64;
typedef unsigned int       u32;

__device__ __forceinline__ u64 pack2(float x) {
    u64 r; asm("mov.b64 %0, {%1, %2};" : "=l"(r) : "f"(x), "f"(x)); return r;
}
__device__ __forceinline__ void unpack2(u64 v, float& lo, float& hi) {
    asm("mov.b64 {%0, %1}, %2;" : "=f"(lo), "=f"(hi) : "l"(v));
}
__device__ __forceinline__ float gethalf(u64 v, int which) {
    float lo, hi; unpack2(v, lo, hi); return which ? hi : lo;
}
__device__ __forceinline__ u64 ffma2(u64 a, u64 b, u64 c) {
    u64 d; asm("fma.rn.f32x2 %0, %1, %2, %3;" : "=l"(d) : "l"(a), "l"(b), "l"(c)); return d;
}
__device__ __forceinline__ float silu_f(float v) {
    return __fdividef(v, 1.f + __expf(-v));
}

__device__ __forceinline__ void cpys(float* dst, const float* __restrict__ src, int n) {
    const float4* s4 = (const float4*)src; float4* d4 = (float4*)dst;
    for (int i = threadIdx.x; i < (n >> 2); i += blockDim.x) d4[i] = s4[i];
}

__device__ __forceinline__ u32 smem_u32(const void* p) {
    u32 a;
    asm("{ .reg .u64 t; cvta.to.shared.u64 t, %1; cvt.u32.u64 %0, t; }" : "=r"(a) : "l"(p));
    return a;
}

// mma.sync m16n8k16 bf16 (generic HMMA)
__device__ __forceinline__ void mma_bf16(float d[4], u32 a0, u32 a1, u32 a2, u32 a3,
                                         u32 b0, u32 b1) {
    asm volatile("mma.sync.aligned.m16n8k16.row.col.f32.bf16.bf16.f32 "
                 "{%0,%1,%2,%3}, {%4,%5,%6,%7}, {%8,%9}, {%0,%1,%2,%3};"
                 : "+f"(d[0]), "+f"(d[1]), "+f"(d[2]), "+f"(d[3])
                 : "r"(a0), "r"(a1), "r"(a2), "r"(a3), "r"(b0), "r"(b1));
}

#define LDMX4(r, addr) \
    asm volatile("ldmatrix.sync.aligned.m8n8.x4.shared.b16 {%0,%1,%2,%3}, [%4];" \
                 : "=r"((r)[0]), "=r"((r)[1]), "=r"((r)[2]), "=r"((r)[3]) : "r"(addr))

// ---------------- k_msg SMEM layout (bytes), K=128 A tile; H overlays dead A ----------------
#define SA2 136  // bf16 stride; 272 B = 16 mod 128 -> ldmatrix conflict-free
#define SH  72   // 144 B = 16 mod 128
#define SM_AH   0
#define SM_AL   34816
#define SM_HH   0
#define SM_HL   18432
#define SM_B1V  69632
#define SM_B2V  69888
#define SM_DSV  70144
#define SM_BTS  70656
#define SM_MSG_TOTAL 71168

__device__ __forceinline__ void split_store(char* smb, int hio, int loo, int stride,
                                            int r, int k, float f0, float f1) {
    __nv_bfloat162 h = __floats2bfloat162_rn(f0, f1);
    __nv_bfloat162 l = __floats2bfloat162_rn(f0 - __bfloat162float(h.x),
                                             f1 - __bfloat162float(h.y));
    int off = (r * stride + k) * 2;
    *(u32*)(smb + hio + off) = *(u32*)&h;
    *(u32*)(smb + loo + off) = *(u32*)&l;
}

__device__ __forceinline__ void conv_row16a(char* smb, const float* __restrict__ src,
                                            int r, int kbase) {
    const float4* s4 = (const float4*)src;
    #pragma unroll
    for (int j = 0; j < 16; j++) {
        float4 v = s4[j];
        int k = kbase + 4 * j;
        split_store(smb, SM_AH, SM_AL, SA2, r, k, v.x, v.y);
        split_store(smb, SM_AH, SM_AL, SA2, r, k + 2, v.z, v.w);
    }
}

// ---------------- kernels ----------------

__global__ void k_zero(int E) {
    int stride = gridDim.x * blockDim.x;
    for (int i = blockIdx.x * blockDim.x + threadIdx.x; i < E * 64; i += stride)
        g_aggr[i] = 0.f;
    int i = blockIdx.x * blockDim.x + threadIdx.x;
    if (i < E) g_deg[i] = 0.f;
    if (i < GMAX * 64) g_gsum[i] = 0.f;
    if (i < GMAX) g_gcnt[i] = 0.f;
}

__global__ void k_deg(const int* __restrict__ bei, int BE) {
    int b = blockIdx.x * blockDim.x + threadIdx.x;
    if (b < BE) atomicAdd(&g_deg[bei[BE + b]], 1.f);
}

// Pre-pack W1/W2 (hi/lo splits) into mma-b-fragment order, plus te @ W1[128:192].
// Needs 6144 + 2048 + 512 = 8704 threads.
__global__ void k_wconv(const float* __restrict__ mw1, const float* __restrict__ mw2,
                        const float* __restrict__ emb) {
    int i = blockIdx.x * blockDim.x + threadIdx.x;
    int lane = i & 31;
    int g = lane >> 2, qi = lane & 3;

    auto packfrag = [&](const float* W, int s, int ks, int img) {
        uint4 v; u32* pv = (u32*)&v;
        #pragma unroll
        for (int nt = 0; nt < 2; nt++) {
            int n = s * 16 + nt * 8 + g;
            #pragma unroll
            for (int bi = 0; bi < 2; bi++) {
                int k = ks * 16 + bi * 8 + 2 * qi;
                float w0 = W[k * 64 + n], w1v = W[(k + 1) * 64 + n];
                __nv_bfloat16 h0 = __float2bfloat16_rn(w0), h1 = __float2bfloat16_rn(w1v);
                __nv_bfloat162 o;
                if (img == 0) { o.x = h0; o.y = h1; }
                else {
                    o.x = __float2bfloat16_rn(w0 - __bfloat162float(h0));
                    o.y = __float2bfloat16_rn(w1v - __bfloat162float(h1));
                }
                pv[nt * 2 + bi] = *(u32*)&o;
            }
        }
        return v;
    };

    if (i < 6144) {
        int t = i >> 5;
        int ks = t % 12; t /= 12;
        int s = t & 3; t >>= 2;
        int img = t & 1, l = t >> 1;
        g_w1f[l][img][s][ks][lane] = packfrag(mw1 + l * 12288, s, ks, img);
        return;
    }
    int i2 = i - 6144;
    if (i2 >= 0 && i2 < 2048) {
        int t = i2 >> 5;
        int ks = t & 3; t >>= 2;
        int s = t & 3; t >>= 2;
        int img = t & 1, l = t >> 1;
        g_w2f[l][img][s][ks][lane] = packfrag(mw2 + l * 4096, s, ks, img);
        return;
    }
    int i3 = i2 - 2048;
    if (i3 >= 0 && i3 < 512) {   // te precompute: 2l x 4bt x 64n
        int n = i3 & 63, bt = (i3 >> 6) & 3, l = i3 >> 8;
        const float* te = emb + l * 320 + bt * 64;
        const float* W = mw1 + l * 12288;
        float s = 0.f;
        #pragma unroll 8
        for (int k = 0; k < 64; k++) s += te[k] * W[(128 + k) * 64 + n];
        g_te[l][bt][n] = s;
    }
}

// ---------- scalar GEMM pieces (init/upd) ----------

template<int KK, int STR>
__device__ __forceinline__ void gemm_acc(const float* As, const float* Ws,
                                         int eg, int cg, u64 acc[2][4]) {
    const float* ap = As + eg * 4;
    const float* wp = Ws + cg * 4;
    #pragma unroll 4
    for (int k = 0; k < KK; k++) {
        ulonglong2 av = *(const ulonglong2*)(ap + k * STR);
        float4 wv = *(const float4*)(wp + k * 64);
        u64 w0 = pack2(wv.x), w1 = pack2(wv.y), w2 = pack2(wv.z), w3 = pack2(wv.w);
        acc[0][0] = ffma2(av.x, w0, acc[0][0]); acc[0][1] = ffma2(av.x, w1, acc[0][1]);
        acc[0][2] = ffma2(av.x, w2, acc[0][2]); acc[0][3] = ffma2(av.x, w3, acc[0][3]);
        acc[1][0] = ffma2(av.y, w0, acc[1][0]); acc[1][1] = ffma2(av.y, w1, acc[1][1]);
        acc[1][2] = ffma2(av.y, w2, acc[1][2]); acc[1][3] = ffma2(av.y, w3, acc[1][3]);
    }
}

__device__ __forceinline__ void bias_init(const float* __restrict__ b, int cg, u64 acc[2][4]) {
    float4 bv = *(const float4*)(b + cg * 4);
    acc[0][0] = acc[1][0] = pack2(bv.x);
    acc[0][1] = acc[1][1] = pack2(bv.y);
    acc[0][2] = acc[1][2] = pack2(bv.z);
    acc[0][3] = acc[1][3] = pack2(bv.w);
}

template<int STR>
__device__ __forceinline__ void silu_store(const u64 acc[2][4], float* Hs, int eg, int cg) {
    #pragma unroll
    for (int c = 0; c < 4; c++) {
        float x0, x1, x2, x3;
        unpack2(acc[0][c], x0, x1); unpack2(acc[1][c], x2, x3);
        float4 hv = make_float4(silu_f(x0), silu_f(x1), silu_f(x2), silu_f(x3));
        *(float4*)(Hs + (cg * 4 + c) * STR + eg * 4) = hv;
    }
}

// bond_init: 64 edges/CTA, 256 threads (scalar)
extern "C" __global__ void __launch_bounds__(256, 1)
k_init(const float* __restrict__ af, const int* __restrict__ eidx,
       const float* __restrict__ iw1, const float* __restrict__ ib1,
       const float* __restrict__ iw2, const float* __restrict__ ib2, int E) {
    extern __shared__ float sm[];
    float* W1s = sm;
    float* W2s = sm + 16384;
    float* As  = sm + 20480;
    float* Hs  = sm + 20480 + 17408;
    cpys(W1s, iw1, 16384); cpys(W2s, iw2, 4096);

    int tid = threadIdx.x;
    int e_loc = tid >> 2, p = tid & 3;
    int e = blockIdx.x * IT + e_loc;
    int ec = (e < E) ? e : 0;
    int r = eidx[ec], c = eidx[E + ec];
    const float* hi = af + (size_t)r * 128;
    const float* hj = af + (size_t)c * 128;
    #pragma unroll
    for (int i = 0; i < 8; i++) {
        int j = p + 4 * i;
        float4 v = ((const float4*)hi)[j];
        int k = 4 * j;
        As[(k + 0) * ISTR + e_loc] = v.x; As[(k + 1) * ISTR + e_loc] = v.y;
        As[(k + 2) * ISTR + e_loc] = v.z; As[(k + 3) * ISTR + e_loc] = v.w;
    }
    #pragma unroll
    for (int i = 0; i < 8; i++) {
        int j = p + 4 * i;
        float4 v = ((const float4*)hj)[j];
        int k = 128 + 4 * j;
        As[(k + 0) * ISTR + e_loc] = v.x; As[(k + 1) * ISTR + e_loc] = v.y;
        As[(k + 2) * ISTR + e_loc] = v.z; As[(k + 3) * ISTR + e_loc] = v.w;
    }
    __syncthreads();

    {
        float dot = 0.f, ni = 0.f, nj = 0.f;
        #pragma unroll 8
        for (int t = 0; t < 32; t++) {
            int k = p * 32 + t;
            float a = As[k * ISTR + e_loc];
            float b = As[(128 + k) * ISTR + e_loc];
            dot += a * b; ni += a * a; nj += b * b;
        }
        dot += __shfl_xor_sync(~0u, dot, 1); dot += __shfl_xor_sync(~0u, dot, 2);
        ni  += __shfl_xor_sync(~0u, ni, 1);  ni  += __shfl_xor_sync(~0u, ni, 2);
        nj  += __shfl_xor_sync(~0u, nj, 1);  nj  += __shfl_xor_sync(~0u, nj, 2);
        if (p == 0 && e < E) {
            float a = fmaxf(sqrtf(ni), 1e-8f), b = fmaxf(sqrtf(nj), 1e-8f);
            float sim = dot / (a * b);
            int bt = 0;
            if (sim > 0.8f) bt = 1;
            if (sim > 0.9f) bt = 2;
            if (sim < 0.3f) bt = 3;
            g_bt[e] = bt;
        }
    }

    int eg = tid >> 4, cg = tid & 15;
    u64 a1[2][4]; bias_init(ib1, cg, a1);
    gemm_acc<256, ISTR>(As, W1s, eg, cg, a1);
    silu_store<ISTR>(a1, Hs, eg, cg);
    __syncthreads();
    u64 o[2][4]; bias_init(ib2, cg, o);
    gemm_acc<64, ISTR>(Hs, W2s, eg, cg, o);

    int ebase = blockIdx.x * IT + eg * 4;
    #pragma unroll
    for (int j = 0; j < 4; j++) {
        if (ebase + j < E) {
            float4 v;
            v.x = gethalf(o[j >> 1][0], j & 1); v.y = gethalf(o[j >> 1][1], j & 1);
            v.z = gethalf(o[j >> 1][2], j & 1); v.w = gethalf(o[j >> 1][3], j & 1);
            *(float4*)(g_x + (size_t)(ebase + j) * 64 + cg * 4) = v;
        }
    }
}

// ---------- HMMA message MLP: 128 edges/CTA, 256 threads, 2 CTAs/SM, K=128 ----------
extern "C" __global__ void __launch_bounds__(256, 2)
k_msg(const int* __restrict__ bei, int layer,
      const float* __restrict__ mb1, const float* __restrict__ mb2, int BE) {
    extern __shared__ char smb[];
    u32 sb = smem_u32(smb);
    int tid = threadIdx.x, wid = tid >> 5, lane = tid & 31;
    int g = lane >> 2, qi = lane & 3;
    int* ds  = (int*)(smb + SM_DSV);
    int* bts = (int*)(smb + SM_BTS);
    float* b1s = (float*)(smb + SM_B1V);
    float* b2s = (float*)(smb + SM_B2V);

    if (tid < 64) b1s[tid] = mb1[tid];
    else if (tid < 128) b2s[tid - 64] = mb2[tid - 64];

    // gather + split A [128 rows][128 k] = [xd | xs]; balanced 1 row/thread
    int ebase0 = blockIdx.x * MT;
    int row = tid & 127;
    int e = ebase0 + row;
    int ec = (e < BE) ? e : 0;
    if (tid < 128) {
        int d = bei[BE + ec];
        ds[row] = d;
        bts[row] = g_bt[d];
        conv_row16a(smb, g_x + (size_t)d * 64, row, 0);
    } else {
        int s = bei[ec];
        conv_row16a(smb, g_x + (size_t)s * 64, row, 64);
    }
    __syncthreads();

    int mbase = (wid & 3) * 32;
    int ns0 = (wid >> 2) * 2;
    int nbase = ns0 * 16;
    int a_row = lane & 15;
    int a_koff = (lane >> 4) * 8;

    float d_[2][4][4];
    #pragma unroll
    for (int mt = 0; mt < 2; mt++)
        #pragma unroll
        for (int nt = 0; nt < 4; nt++)
            #pragma unroll
            for (int x = 0; x < 4; x++) d_[mt][nt][x] = 0.f;

    // GEMM1: K=128, 3 splits x 8 ksteps
    {
        const int AIMG[3] = {SM_AH, SM_AH, SM_AL};
        const int BIMG[3] = {0, 1, 0};
        #pragma unroll 1
        for (int sp = 0; sp < 3; sp++) {
            u32 Ab = sb + AIMG[sp];
            const uint4* B0 = &g_w1f[layer][BIMG[sp]][ns0][0][lane];
            const uint4* B1 = &g_w1f[layer][BIMG[sp]][ns0 + 1][0][lane];
            #pragma unroll 2
            for (int ks = 0; ks < 8; ks++) {
                int k0 = ks * 16;
                uint4 bv0 = __ldg(B0 + ks * 32);
                uint4 bv1 = __ldg(B1 + ks * 32);
                u32 af[2][4];
                #pragma unroll
                for (int mt = 0; mt < 2; mt++)
                    LDMX4(af[mt], Ab + ((mbase + mt * 16 + a_row) * SA2 + k0 + a_koff) * 2);
                #pragma unroll
                for (int mt = 0; mt < 2; mt++) {
                    mma_bf16(d_[mt][0], af[mt][0], af[mt][1], af[mt][2], af[mt][3], bv0.x, bv0.y);
                    mma_bf16(d_[mt][1], af[mt][0], af[mt][1], af[mt][2], af[mt][3], bv0.z, bv0.w);
                    mma_bf16(d_[mt][2], af[mt][0], af[mt][1], af[mt][2], af[mt][3], bv1.x, bv1.y);
                    mma_bf16(d_[mt][3], af[mt][0], af[mt][1], af[mt][2], af[mt][3], bv1.z, bv1.w);
                }
            }
        }
    }
    __syncthreads();   // A dead; H overlays it

    // epilogue1: bias + te-lookup + silu + split into H
    #pragma unroll
    for (int mt = 0; mt < 2; mt++) {
        int r0 = mbase + mt * 16 + g;
        const float* te0 = g_te[layer][bts[r0]];
        const float* te1 = g_te[layer][bts[r0 + 8]];
        #pragma unroll
        for (int nt = 0; nt < 4; nt++) {
            int c0 = nbase + nt * 8 + 2 * qi;
            float bA = b1s[c0], bB = b1s[c0 + 1];
            float2 t0 = *(const float2*)(te0 + c0);
            float2 t1 = *(const float2*)(te1 + c0);
            float f0 = silu_f(d_[mt][nt][0] + bA + t0.x), f1 = silu_f(d_[mt][nt][1] + bB + t0.y);
            float f2 = silu_f(d_[mt][nt][2] + bA + t1.x), f3 = silu_f(d_[mt][nt][3] + bB + t1.y);
            split_store(smb, SM_HH, SM_HL, SH, r0, c0, f0, f1);
            split_store(smb, SM_HH, SM_HL, SH, r0 + 8, c0, f2, f3);
        }
    }
    __syncthreads();

    // GEMM2: K=64, 3 splits x 4 ksteps
    #pragma unroll
    for (int mt = 0; mt < 2; mt++)
        #pragma unroll
        for (int nt = 0; nt < 4; nt++)
            #pragma unroll
            for (int x = 0; x < 4; x++) d_[mt][nt][x] = 0.f;
    {
        const int AIMG2[3] = {SM_HH, SM_HH, SM_HL};
        const int BIMG2[3] = {0, 1, 0};
        #pragma unroll 1
        for (int sp = 0; sp < 3; sp++) {
            u32 Ab = sb + AIMG2[sp];
            const uint4* B0 = &g_w2f[layer][BIMG2[sp]][ns0][0][lane];
            const uint4* B1 = &g_w2f[layer][BIMG2[sp]][ns0 + 1][0][lane];
            #pragma unroll 2
            for (int ks = 0; ks < 4; ks++) {
                int k0 = ks * 16;
                uint4 bv0 = __ldg(B0 + ks * 32);
                uint4 bv1 = __ldg(B1 + ks * 32);
                u32 af[2][4];
                #pragma unroll
                for (int mt = 0; mt < 2; mt++)
                    LDMX4(af[mt], Ab + ((mbase + mt * 16 + a_row) * SH + k0 + a_koff) * 2);
                #pragma unroll
                for (int mt = 0; mt < 2; mt++) {
                    mma_bf16(d_[mt][0], af[mt][0], af[mt][1], af[mt][2], af[mt][3], bv0.x, bv0.y);
                    mma_bf16(d_[mt][1], af[mt][0], af[mt][1], af[mt][2], af[mt][3], bv0.z, bv0.w);
                    mma_bf16(d_[mt][2], af[mt][0], af[mt][1], af[mt][2], af[mt][3], bv1.x, bv1.y);
                    mma_bf16(d_[mt][3], af[mt][0], af[mt][1], af[mt][2], af[mt][3], bv1.z, bv1.w);
                }
            }
        }
    }

    // epilogue2: bias + RED v2 scatter-add to aggr[dst]
    #pragma unroll
    for (int mt = 0; mt < 2; mt++) {
        int r0 = mbase + mt * 16 + g;
        int dd0 = ds[r0], dd1 = ds[r0 + 8];
        bool v0 = (ebase0 + r0 < BE), v1 = (ebase0 + r0 + 8 < BE);
        #pragma unroll
        for (int nt = 0; nt < 4; nt++) {
            int c0 = nbase + nt * 8 + 2 * qi;
            float bA = b2s[c0], bB = b2s[c0 + 1];
            if (v0) {
                asm volatile("red.global.add.v2.f32 [%0], {%1,%2};"
                             :: "l"(g_aggr + (size_t)dd0 * 64 + c0),
                                "f"(d_[mt][nt][0] + bA), "f"(d_[mt][nt][1] + bB) : "memory");
            }
            if (v1) {
                asm volatile("red.global.add.v2.f32 [%0], {%1,%2};"
                             :: "l"(g_aggr + (size_t)dd1 * 64 + c0),
                                "f"(d_[mt][nt][2] + bA), "f"(d_[mt][nt][3] + bB) : "memory");
            }
        }
    }
}

// update MLP: 128 edges/CTA, 512 threads (scalar); zeroes aggr after reading.
extern "C" __global__ void __launch_bounds__(512, 1)
k_upd(const float* __restrict__ uw1, const float* __restrict__ ub1,
      const float* __restrict__ uw2, const float* __restrict__ ub2, int E) {
    extern __shared__ float sm[];
    float* W1s = sm;
    float* W2s = sm + 8192;
    float* As  = sm + 12288;
    float* Hs  = sm + 12288 + 16896;
    cpys(W1s, uw1, 8192); cpys(W2s, uw2, 4096);

    int tid = threadIdx.x;
    int e_loc = tid >> 2, p = tid & 3;
    int e = blockIdx.x * MT + e_loc;
    int ec = (e < E) ? e : 0;
    float rdiv = 1.f / fmaxf(g_deg[ec], 1.f);
    float* arow = g_aggr + (size_t)ec * 64;
    const float* xrow = g_x + (size_t)ec * 64;
    #pragma unroll
    for (int i = 0; i < 4; i++) {
        int j = p + 4 * i;
        float4 v = ((const float4*)arow)[j];
        int k = 4 * j;
        As[(k + 0) * MSTR + e_loc] = v.x * rdiv; As[(k + 1) * MSTR + e_loc] = v.y * rdiv;
        As[(k + 2) * MSTR + e_loc] = v.z * rdiv; As[(k + 3) * MSTR + e_loc] = v.w * rdiv;
        if (e < E) ((float4*)arow)[j] = make_float4(0.f, 0.f, 0.f, 0.f);
    }
    #pragma unroll
    for (int i = 0; i < 4; i++) {
        int j = p + 4 * i;
        float4 v = ((const float4*)xrow)[j];
        int k = 64 + 4 * j;
        As[(k + 0) * MSTR + e_loc] = v.x; As[(k + 1) * MSTR + e_loc] = v.y;
        As[(k + 2) * MSTR + e_loc] = v.z; As[(k + 3) * MSTR + e_loc] = v.w;
    }
    __syncthreads();

    int eg = tid >> 4, cg = tid & 15;
    u64 a1[2][4]; bias_init(ub1, cg, a1);
    gemm_acc<128, MSTR>(As, W1s, eg, cg, a1);
    silu_store<MSTR>(a1, Hs, eg, cg);
    __syncthreads();
    u64 o[2][4]; bias_init(ub2, cg, o);
    gemm_acc<64, MSTR>(Hs, W2s, eg, cg, o);

    int ebase = blockIdx.x * MT + eg * 4;
    #pragma unroll
    for (int j = 0; j < 4; j++) {
        if (ebase + j < E) {
            float* xp = g_x + (size_t)(ebase + j) * 64 + cg * 4;
            float4 xv = *(float4*)xp;
            xv.x += gethalf(o[j >> 1][0], j & 1); xv.y += gethalf(o[j >> 1][1], j & 1);
            xv.z += gethalf(o[j >> 1][2], j & 1); xv.w += gethalf(o[j >> 1][3], j & 1);
            *(float4*)xp = xv;
        }
    }
}

// pooling: per-edge float4 RED of x into gsum; cc==0 thread also counts the edge.
__global__ void k_pool2(const int* __restrict__ eidx, const int* __restrict__ batch, int E) {
    int i = blockIdx.x * blockDim.x + threadIdx.x;
    if (i >= E * 16) return;
    int e = i >> 4, cc = i & 15;
    int gph = batch[eidx[e]];
    if (cc == 0) atomicAdd(&g_gcnt[gph], 1.f);
    float4 v = ((const float4*)g_x)[(size_t)e * 16 + cc];
    float* dst = g_gsum + gph * 64 + cc * 4;
    asm volatile("red.global.add.v4.f32 [%0], {%1,%2,%3,%4};"
                 :: "l"(dst), "f"(v.x), "f"(v.y), "f"(v.z), "f"(v.w) : "memory");
}

// fused final: copy x to out[0..E*64) and write pooled features at out[E*64..]
__global__ void k_fin2(float* __restrict__ out, int E, int G) {
    int i = blockIdx.x * blockDim.x + threadIdx.x;
    int n4 = E * 16;
    const float4* src = (const float4*)g_x;
    float4* dst = (float4*)out;
    for (int j = i; j < n4; j += gridDim.x * blockDim.x) dst[j] = src[j];
    if (i < G * 64) out[(size_t)E * 64 + i] = g_gsum[i] / fmaxf(g_gcnt[i >> 6], 1.f);
}

// ---------------- host launcher ----------------

extern "C" void kernel_launch(void* const* d_in, const int* in_sizes, int n_in,
                              void* d_out, int out_size) {
    const float* af    = (const float*)d_in[0];
    const int*   batch = (const int*)d_in[3];
    const int*   eidx  = (const int*)d_in[4];
    const int*   bei   = (const int*)d_in[5];
    const float* iw1 = (const float*)d_in[6];
    const float* ib1 = (const float*)d_in[7];
    const float* iw2 = (const float*)d_in[8];
    const float* ib2 = (const float*)d_in[9];
    const float* emb = (const float*)d_in[10];
    const float* mw1 = (const float*)d_in[11];
    const float* mb1 = (const float*)d_in[12];
    const float* mw2 = (const float*)d_in[13];
    const float* mb2 = (const float*)d_in[14];
    const float* uw1 = (const float*)d_in[15];
    const float* ub1 = (const float*)d_in[16];
    const float* uw2 = (const float*)d_in[17];
    const float* ub2 = (const float*)d_in[18];

    int E  = in_sizes[4] / 2;
    int BE = in_sizes[5] / 2;
    int G  = out_size / 64 - E;

    const int SH_INIT = (16384 + 4096 + 256 * ISTR + 64 * ISTR) * 4;
    const int SH_UPD  = (8192 + 4096 + 128 * MSTR + 64 * MSTR) * 4;
    cudaFuncSetAttribute(k_init, cudaFuncAttributeMaxDynamicSharedMemorySize, SH_INIT);
    cudaFuncSetAttribute(k_msg,  cudaFuncAttributeMaxDynamicSharedMemorySize, SM_MSG_TOTAL);
    cudaFuncSetAttribute(k_upd,  cudaFuncAttributeMaxDynamicSharedMemorySize, SH_UPD);

    int gI = (E + IT - 1) / IT;
    int gM = (BE + MT - 1) / MT;
    int gU = (E + MT - 1) / MT;
    int gBE256 = (BE + 255) / 256;

    k_zero<<<2048, 256>>>(E);
    k_wconv<<<34, 256>>>(mw1, mw2, emb);
    k_init<<<gI, 256, SH_INIT>>>(af, eidx, iw1, ib1, iw2, ib2, E);
    k_deg<<<gBE256, 256>>>(bei, BE);

    for (int l = 0; l < 2; l++) {
        k_msg<<<gM, 256, SM_MSG_TOTAL>>>(bei, l, mb1 + l * 64, mb2 + l * 64, BE);
        k_upd<<<gU, 512, SH_UPD>>>(uw1 + l * 8192, ub1 + l * 64,
                                   uw2 + l * 4096, ub2 + l * 64, E);
    }

    k_pool2<<<(E * 16 + 255) / 256, 256>>>(eidx, batch, E);
    k_fin2<<<1024, 256>>>((float*)d_out, E, G);
}